// round 2
// baseline (speedup 1.0000x reference)
#include <cuda_runtime.h>

// PrimaryCaps: 3x GEMM [16384,768]x[768,512] + bias + squash(groups of 8)
// Output col n = r*8 + c maps contiguously: out[b, m*512 + n], row stride 1536.
//
// Tile: BM=128 x BN=256, BK=16. 512 threads, 8x8 microtile.
// tx = tid%32 covers cols [n0+tx*8, n0+tx*8+8)  (= one full squash group per row)
// ty = tid/32 covers rows [b0+ty*8, b0+ty*8+8)

#define BM 128
#define BN 256
#define BK 16

#define BATCH 16384
#define IN_CH 768
#define OUT_ROW 1536   // 3*512 floats per batch row

__global__ __launch_bounds__(512, 1)
void primarycaps_kernel(const float* __restrict__ x_img,
                        const float* __restrict__ x_capt,
                        const float* __restrict__ x_dct,
                        const float* __restrict__ w_img,
                        const float* __restrict__ b_img,
                        const float* __restrict__ w_capt,
                        const float* __restrict__ b_capt,
                        const float* __restrict__ w_dct,
                        const float* __restrict__ b_dct,
                        float* __restrict__ out)
{
    __shared__ float As[BK][BM + 4];   // +4 pad keeps 16B align, shifts banks
    __shared__ float Bs[BK][BN + 4];

    const int tid = threadIdx.x;
    const int tx  = tid & 31;          // N dim: 32 groups of 8 cols
    const int ty  = tid >> 5;          // M dim: 16 groups of 8 rows

    const int b0 = blockIdx.x * BM;    // batch tile
    const int n0 = blockIdx.y * BN;    // column tile (0 or 256)
    const int m  = blockIdx.z;         // modality

    const float* X;  const float* W;  const float* Bv;
    if (m == 0)      { X = x_img;  W = w_img;  Bv = b_img;  }
    else if (m == 1) { X = x_capt; W = w_capt; Bv = b_capt; }
    else             { X = x_dct;  W = w_dct;  Bv = b_dct;  }

    // ---- precompute global load coordinates ----
    // A: each thread loads one float4: row = tid/4, kq = tid%4
    const int a_row = tid >> 2;
    const int a_kq  = (tid & 3) * 4;
    const float* a_gptr = X + (size_t)(b0 + a_row) * IN_CH + a_kq;

    // B: each thread loads two float4: idx = q*512 + tid; n_local = idx/4, kq = idx%4
    // weight row for output col n: ((n&7)*64 + (n>>3)) * 768
    int   b_nl[2], b_kq[2];
    const float* b_gptr[2];
    #pragma unroll
    for (int q = 0; q < 2; ++q) {
        int idx  = q * 512 + tid;
        b_nl[q]  = idx >> 2;
        b_kq[q]  = (idx & 3) * 4;
        int n    = n0 + b_nl[q];
        int wrow = ((n & 7) << 6) + (n >> 3);
        b_gptr[q] = W + (size_t)wrow * IN_CH + b_kq[q];
    }

    float acc[8][8];
    #pragma unroll
    for (int i = 0; i < 8; ++i)
        #pragma unroll
        for (int j = 0; j < 8; ++j)
            acc[i][j] = 0.0f;

    for (int k0 = 0; k0 < IN_CH; k0 += BK) {
        // ---- global -> shared ----
        {
            float4 av = *(const float4*)(a_gptr + k0);
            As[a_kq + 0][a_row] = av.x;
            As[a_kq + 1][a_row] = av.y;
            As[a_kq + 2][a_row] = av.z;
            As[a_kq + 3][a_row] = av.w;
            #pragma unroll
            for (int q = 0; q < 2; ++q) {
                float4 bv = *(const float4*)(b_gptr[q] + k0);
                Bs[b_kq[q] + 0][b_nl[q]] = bv.x;
                Bs[b_kq[q] + 1][b_nl[q]] = bv.y;
                Bs[b_kq[q] + 2][b_nl[q]] = bv.z;
                Bs[b_kq[q] + 3][b_nl[q]] = bv.w;
            }
        }
        __syncthreads();

        // ---- compute ----
        #pragma unroll 4
        for (int k = 0; k < BK; ++k) {
            float4 a0 = *(const float4*)&As[k][ty * 8];
            float4 a1 = *(const float4*)&As[k][ty * 8 + 4];
            float4 c0 = *(const float4*)&Bs[k][tx * 8];
            float4 c1 = *(const float4*)&Bs[k][tx * 8 + 4];
            float a[8] = {a0.x, a0.y, a0.z, a0.w, a1.x, a1.y, a1.z, a1.w};
            float b[8] = {c0.x, c0.y, c0.z, c0.w, c1.x, c1.y, c1.z, c1.w};
            #pragma unroll
            for (int i = 0; i < 8; ++i)
                #pragma unroll
                for (int j = 0; j < 8; ++j)
                    acc[i][j] = fmaf(a[i], b[j], acc[i][j]);
        }
        __syncthreads();
    }

    // ---- epilogue: bias + squash over the 8 cols each thread owns ----
    // col n = n0 + tx*8 + j -> c = j, r = n0/8 + tx
    const int gr = (n0 >> 3) + tx;
    float bias[8];
    #pragma unroll
    for (int j = 0; j < 8; ++j)
        bias[j] = Bv[j * 64 + gr];

    float* orow = out + (size_t)(b0 + ty * 8) * OUT_ROW + m * 512 + n0 + tx * 8;

    #pragma unroll
    for (int i = 0; i < 8; ++i) {
        float u[8];
        float sq = 0.0f;
        #pragma unroll
        for (int j = 0; j < 8; ++j) {
            u[j] = acc[i][j] + bias[j];
            sq = fmaf(u[j], u[j], sq);
        }
        float scale = sq / ((1.0f + sq) * sqrtf(sq + 1e-7f));
        float4 o0 = make_float4(u[0]*scale, u[1]*scale, u[2]*scale, u[3]*scale);
        float4 o1 = make_float4(u[4]*scale, u[5]*scale, u[6]*scale, u[7]*scale);
        *(float4*)(orow + (size_t)i * OUT_ROW)     = o0;
        *(float4*)(orow + (size_t)i * OUT_ROW + 4) = o1;
    }
}

extern "C" void kernel_launch(void* const* d_in, const int* in_sizes, int n_in,
                              void* d_out, int out_size)
{
    const float* x_img  = (const float*)d_in[0];
    const float* x_capt = (const float*)d_in[1];
    const float* x_dct  = (const float*)d_in[2];
    const float* w_img  = (const float*)d_in[3];
    const float* b_img  = (const float*)d_in[4];
    const float* w_capt = (const float*)d_in[5];
    const float* b_capt = (const float*)d_in[6];
    const float* w_dct  = (const float*)d_in[7];
    const float* b_dct  = (const float*)d_in[8];
    float* out = (float*)d_out;

    dim3 grid(BATCH / BM, 512 / BN, 3);   // (128, 2, 3)
    dim3 block(512);
    primarycaps_kernel<<<grid, block>>>(x_img, x_capt, x_dct,
                                        w_img, b_img, w_capt, b_capt, w_dct, b_dct,
                                        out);
}

// round 4
// speedup vs baseline: 2.3732x; 2.3732x over previous
#include <cuda_runtime.h>
#include <cuda_bf16.h>
#include <cstdint>

#define IN_CH   768
#define OUT_ROW 1536
#define BM      128
#define BN      128
#define BK      32
#define NCHUNK  24          // 768/32

#define ROWB    80          // padded smem row: 32 bf16 (64B) + 16B pad -> ldmatrix conflict-free
#define PLANE   10240       // 128 rows * 80B
#define STGB    40960       // A_hi A_lo B_hi B_lo
#define SM_STG(s) (1024 + (s)*STGB)
#define OFF_AHI 0
#define OFF_ALO 10240
#define OFF_BHI 20480
#define OFF_BLO 30720
#define SMEM_TOTAL (1024 + 2*STGB)   // 82944 B

// Pre-converted weights, gmem layout identical to smem tile layout (incl. padding):
// [mod 3][ntile 4][kchunk 24][plane 2][128 rows][80 B]
__device__ __align__(128) unsigned char g_Bscr[3*4*24*2*PLANE];

static __device__ __forceinline__ uint32_t s2u(const void* p) {
    uint32_t a;
    asm("{ .reg .u64 t; cvta.to.shared.u64 t, %1; cvt.u32.u64 %0, t; }" : "=r"(a) : "l"(p));
    return a;
}
static __device__ __forceinline__ void ldsm4(uint32_t* r, uint32_t addr) {
    asm volatile("ldmatrix.sync.aligned.m8n8.x4.shared.b16 {%0,%1,%2,%3}, [%4];"
                 : "=r"(r[0]), "=r"(r[1]), "=r"(r[2]), "=r"(r[3]) : "r"(addr));
}
static __device__ __forceinline__ void mma16816(float* c, const uint32_t* a, const uint32_t* b) {
    asm volatile("mma.sync.aligned.m16n8k16.row.col.f32.bf16.bf16.f32 "
                 "{%0,%1,%2,%3}, {%4,%5,%6,%7}, {%8,%9}, {%0,%1,%2,%3};"
                 : "+f"(c[0]), "+f"(c[1]), "+f"(c[2]), "+f"(c[3])
                 : "r"(a[0]), "r"(a[1]), "r"(a[2]), "r"(a[3]), "r"(b[0]), "r"(b[1]));
}
static __device__ __forceinline__ void cp16(uint32_t dst, const void* src) {
    asm volatile("cp.async.cg.shared.global [%0], [%1], 16;" :: "r"(dst), "l"(src) : "memory");
}
#define CP_COMMIT asm volatile("cp.async.commit_group;" ::: "memory")
#define CP_WAIT1  asm volatile("cp.async.wait_group 1;" ::: "memory")
#define CP_WAIT0  asm volatile("cp.async.wait_group 0;" ::: "memory")

// fp32 -> packed bf16 (hi, lo) for two values; lo = rn(x - hi)
static __device__ __forceinline__ void split2(float x, float y, uint32_t& hi, uint32_t& lo) {
    __nv_bfloat16 hx = __float2bfloat16_rn(x);
    __nv_bfloat16 hy = __float2bfloat16_rn(y);
    float rx = x - __bfloat162float(hx);
    float ry = y - __bfloat162float(hy);
    __nv_bfloat162 h; h.x = hx; h.y = hy;
    __nv_bfloat162 l; l.x = __float2bfloat16_rn(rx); l.y = __float2bfloat16_rn(ry);
    hi = *reinterpret_cast<uint32_t*>(&h);
    lo = *reinterpret_cast<uint32_t*>(&l);
}

// ============ kernel 1: weight conversion (per-launch, deterministic) ============
__global__ __launch_bounds__(256)
void caps_convw(const float* __restrict__ w_img,
                const float* __restrict__ w_capt,
                const float* __restrict__ w_dct)
{
    int gt  = blockIdx.x * 256 + threadIdx.x;     // [0, 147456)
    int mod = gt / 49152;
    int r   = gt % 49152;
    int n   = r / 96;                             // output col within modality [0,512)
    int k8  = r % 96;                             // 8-float k group
    const float* W = (mod == 0) ? w_img : (mod == 1) ? w_capt : w_dct;
    int wrow = ((n & 7) << 6) | (n >> 3);         // W row for col n = r*8 + c
    const float4* src = (const float4*)(W + (size_t)wrow * IN_CH + k8 * 8);
    float4 p = src[0], q = src[1];
    uint32_t h[4], l[4];
    split2(p.x, p.y, h[0], l[0]); split2(p.z, p.w, h[1], l[1]);
    split2(q.x, q.y, h[2], l[2]); split2(q.z, q.w, h[3], l[3]);
    int ntile = n >> 7, rloc = n & 127;
    int kchunk = k8 >> 2, kl = k8 & 3;            // 4 k8-groups per 32-k chunk
    size_t base = (size_t)(((mod * 4 + ntile) * 24 + kchunk) * 2) * PLANE;
    uint32_t off = (uint32_t)(rloc * ROWB + kl * 16);
    *(uint4*)(g_Bscr + base + off)         = make_uint4(h[0], h[1], h[2], h[3]);
    *(uint4*)(g_Bscr + base + PLANE + off) = make_uint4(l[0], l[1], l[2], l[3]);
}

// ============ kernel 2: mma.sync GEMM + bias + squash ============
__global__ __launch_bounds__(256, 1)
void caps_gemm(const float* __restrict__ x_img,
               const float* __restrict__ x_capt,
               const float* __restrict__ x_dct,
               const float* __restrict__ b_img,
               const float* __restrict__ b_capt,
               const float* __restrict__ b_dct,
               float* __restrict__ out)
{
    extern __shared__ __align__(1024) unsigned char smem[];
    const uint32_t sb = s2u(smem);
    float* biasS = (float*)smem;

    const int tid  = threadIdx.x;
    const int lane = tid & 31;
    const int w    = tid >> 5;
    const int wm   = w & 3;            // 4 warps over M (32 rows each)
    const int wn   = w >> 2;           // 2 warps over N (64 cols each)
    const int b0   = blockIdx.x * BM;
    const int n0   = blockIdx.y * BN;
    const int mod  = blockIdx.z;

    const float* X  = (mod == 0) ? x_img : (mod == 1) ? x_capt : x_dct;
    const float* Bv = (mod == 0) ? b_img : (mod == 1) ? b_capt : b_dct;

    if (tid < BN) {
        int n = n0 + tid;
        biasS[tid] = Bv[((n & 7) << 6) + (n >> 3)];
    }

    // ---- A load mapping: thread covers row r = tid>>1, 16 k-floats at half h = tid&1
    const int ar = tid >> 1, ah = tid & 1;
    const float* aG = X + (size_t)(b0 + ar) * IN_CH + ah * 16;
    const uint32_t aS = (uint32_t)(ar * ROWB + ah * 32);    // byte off within plane

    // ---- B cp.async mapping: thread copies 5 x 16B, offsets tid*16 + j*4096 over 20480B
    const unsigned char* bG = g_Bscr + (size_t)((mod * 4 + blockIdx.y) * 24) * 2 * PLANE;

    // ---- ldmatrix lane base offsets (within plane) ----
    const uint32_t a_loff = (uint32_t)((wm * 32 + (lane & 7) + ((lane & 8) ? 8 : 0)) * ROWB
                                       + ((lane & 16) ? 16 : 0));
    const uint32_t b_loff = (uint32_t)((wn * 64 + (lane & 7) + ((lane & 16) ? 8 : 0)) * ROWB
                                       + ((lane & 8) ? 16 : 0));

    float acc[2][8][4];
    #pragma unroll
    for (int i = 0; i < 2; ++i)
        #pragma unroll
        for (int j = 0; j < 8; ++j)
            #pragma unroll
            for (int k = 0; k < 4; ++k) acc[i][j][k] = 0.f;

    // ---- prologue: A(0) regs + B(0) cp.async ----
    float4 av[4];
    #pragma unroll
    for (int j = 0; j < 4; ++j) av[j] = *(const float4*)(aG + j * 4);
    {
        const unsigned char* src = bG;                       // chunk 0, both planes
        uint32_t dst = sb + SM_STG(0) + OFF_BHI;
        #pragma unroll
        for (int j = 0; j < 5; ++j)
            cp16(dst + tid * 16 + j * 4096, src + tid * 16 + j * 4096);
    }
    CP_COMMIT;

    for (int i = 0; i < NCHUNK; ++i) {
        const int s = i & 1;
        const uint32_t stg = sb + SM_STG(s);

        if (i + 1 < NCHUNK) {                                // B(i+1) -> other stage
            const unsigned char* src = bG + (size_t)(i + 1) * 2 * PLANE;
            uint32_t dst = sb + SM_STG(s ^ 1) + OFF_BHI;
            #pragma unroll
            for (int j = 0; j < 5; ++j)
                cp16(dst + tid * 16 + j * 4096, src + tid * 16 + j * 4096);
            CP_COMMIT;
        }

        // STS A(i): split fp32 -> hi/lo planes
        {
            uint32_t hi[8], lo[8];
            #pragma unroll
            for (int j = 0; j < 4; ++j) {
                split2(av[j].x, av[j].y, hi[2*j],   lo[2*j]);
                split2(av[j].z, av[j].w, hi[2*j+1], lo[2*j+1]);
            }
            *(uint4*)(smem + SM_STG(s) + OFF_AHI + aS)      = make_uint4(hi[0], hi[1], hi[2], hi[3]);
            *(uint4*)(smem + SM_STG(s) + OFF_AHI + aS + 16) = make_uint4(hi[4], hi[5], hi[6], hi[7]);
            *(uint4*)(smem + SM_STG(s) + OFF_ALO + aS)      = make_uint4(lo[0], lo[1], lo[2], lo[3]);
            *(uint4*)(smem + SM_STG(s) + OFF_ALO + aS + 16) = make_uint4(lo[4], lo[5], lo[6], lo[7]);
        }
        if (i + 1 < NCHUNK) {                                // prefetch A(i+1)
            const float* ap = aG + (size_t)(i + 1) * BK;
            #pragma unroll
            for (int j = 0; j < 4; ++j) av[j] = *(const float4*)(ap + j * 4);
            CP_WAIT1;
        } else {
            CP_WAIT0;
        }
        __syncthreads();

        // ---- compute chunk i ----
        #pragma unroll
        for (int st = 0; st < 2; ++st) {
            uint32_t ahf[2][4], alf[2][4], bhf[4][4], blf[4][4];
            #pragma unroll
            for (int mt = 0; mt < 2; ++mt) {
                uint32_t base = stg + a_loff + mt * (16 * ROWB) + st * 32;
                ldsm4(ahf[mt], base + OFF_AHI);
                ldsm4(alf[mt], base + OFF_ALO);
            }
            #pragma unroll
            for (int g = 0; g < 4; ++g) {
                uint32_t base = stg + b_loff + g * (16 * ROWB) + st * 32;
                ldsm4(bhf[g], base + OFF_BHI);
                ldsm4(blf[g], base + OFF_BLO);
            }
            #pragma unroll
            for (int mt = 0; mt < 2; ++mt)
                #pragma unroll
                for (int nt = 0; nt < 8; ++nt) {
                    float* c = acc[mt][nt];
                    const uint32_t* BH = &bhf[nt >> 1][(nt & 1) * 2];
                    const uint32_t* BL = &blf[nt >> 1][(nt & 1) * 2];
                    mma16816(c, ahf[mt], BH);   // hi*hi
                    mma16816(c, ahf[mt], BL);   // hi*lo
                    mma16816(c, alf[mt], BH);   // lo*hi
                }
        }
        __syncthreads();
    }

    // ---- epilogue: bias + squash (8-col group == one n8 tile) ----
    const int t4 = lane & 3, g8 = lane >> 2;
    #pragma unroll
    for (int mt = 0; mt < 2; ++mt) {
        const int row0 = b0 + wm * 32 + mt * 16 + g8;
        #pragma unroll
        for (int nt = 0; nt < 8; ++nt) {
            float* c = acc[mt][nt];
            const int cl = wn * 64 + nt * 8 + 2 * t4;        // local col
            const float bx = biasS[cl], by = biasS[cl + 1];
            float u0 = c[0] + bx, u1 = c[1] + by;
            float u2 = c[2] + bx, u3 = c[3] + by;
            float s0 = u0 * u0 + u1 * u1;
            float s1 = u2 * u2 + u3 * u3;
            s0 += __shfl_xor_sync(0xffffffffu, s0, 1);
            s0 += __shfl_xor_sync(0xffffffffu, s0, 2);
            s1 += __shfl_xor_sync(0xffffffffu, s1, 1);
            s1 += __shfl_xor_sync(0xffffffffu, s1, 2);
            float sc0 = s0 / ((1.0f + s0) * sqrtf(s0 + 1e-7f));
            float sc1 = s1 / ((1.0f + s1) * sqrtf(s1 + 1e-7f));
            float* p0 = out + (size_t)row0 * OUT_ROW + mod * 512 + n0 + cl;
            float* p1 = p0 + 8 * OUT_ROW;
            *(float2*)p0 = make_float2(u0 * sc0, u1 * sc0);
            *(float2*)p1 = make_float2(u2 * sc1, u3 * sc1);
        }
    }
}

extern "C" void kernel_launch(void* const* d_in, const int* in_sizes, int n_in,
                              void* d_out, int out_size)
{
    const float* x_img  = (const float*)d_in[0];
    const float* x_capt = (const float*)d_in[1];
    const float* x_dct  = (const float*)d_in[2];
    const float* w_img  = (const float*)d_in[3];
    const float* b_img  = (const float*)d_in[4];
    const float* w_capt = (const float*)d_in[5];
    const float* b_capt = (const float*)d_in[6];
    const float* w_dct  = (const float*)d_in[7];
    const float* b_dct  = (const float*)d_in[8];
    float* out = (float*)d_out;

    cudaFuncSetAttribute(caps_gemm, cudaFuncAttributeMaxDynamicSharedMemorySize, SMEM_TOTAL);

    caps_convw<<<576, 256>>>(w_img, w_capt, w_dct);

    dim3 grid(16384 / BM, 512 / BN, 3);   // (128, 4, 3)
    caps_gemm<<<grid, 256, SMEM_TOTAL>>>(x_img, x_capt, x_dct,
                                         b_img, b_capt, b_dct, out);
}

// round 5
// speedup vs baseline: 3.1168x; 1.3134x over previous
#include <cuda_runtime.h>
#include <cuda_bf16.h>
#include <cstdint>

#define IN_CH   768
#define OUT_ROW 1536
#define BM      128
#define BN      128
#define BK      32
#define NCHUNK  24          // 768/32

#define ROWB    80          // padded smem row: 32 bf16 (64B) + 16B pad -> ldmatrix conflict-free
#define PLANE   10240       // 128 rows * 80B
#define STGB    40960       // A_hi A_lo B_hi B_lo
#define SM_STG(s) (1024 + (s)*STGB)
#define OFF_AHI 0
#define OFF_ALO 10240
#define OFF_BHI 20480
#define OFF_BLO 30720
#define SMEM_TOTAL (1024 + 2*STGB)   // 82944 B -> 2 CTAs/SM

// Pre-converted weights, gmem layout identical to smem tile layout (incl. padding):
// [mod 3][ntile 4][kchunk 24][plane 2][128 rows][80 B]
__device__ __align__(128) unsigned char g_Bscr[3*4*24*2*PLANE];

static __device__ __forceinline__ uint32_t s2u(const void* p) {
    uint32_t a;
    asm("{ .reg .u64 t; cvta.to.shared.u64 t, %1; cvt.u32.u64 %0, t; }" : "=r"(a) : "l"(p));
    return a;
}
static __device__ __forceinline__ void ldsm4(uint32_t* r, uint32_t addr) {
    asm volatile("ldmatrix.sync.aligned.m8n8.x4.shared.b16 {%0,%1,%2,%3}, [%4];"
                 : "=r"(r[0]), "=r"(r[1]), "=r"(r[2]), "=r"(r[3]) : "r"(addr));
}
static __device__ __forceinline__ void mma16816(float* c, const uint32_t* a, const uint32_t* b) {
    asm volatile("mma.sync.aligned.m16n8k16.row.col.f32.bf16.bf16.f32 "
                 "{%0,%1,%2,%3}, {%4,%5,%6,%7}, {%8,%9}, {%0,%1,%2,%3};"
                 : "+f"(c[0]), "+f"(c[1]), "+f"(c[2]), "+f"(c[3])
                 : "r"(a[0]), "r"(a[1]), "r"(a[2]), "r"(a[3]), "r"(b[0]), "r"(b[1]));
}
static __device__ __forceinline__ void cp16(uint32_t dst, const void* src) {
    asm volatile("cp.async.cg.shared.global [%0], [%1], 16;" :: "r"(dst), "l"(src) : "memory");
}
#define CP_COMMIT asm volatile("cp.async.commit_group;" ::: "memory")
#define CP_WAIT1  asm volatile("cp.async.wait_group 1;" ::: "memory")
#define CP_WAIT0  asm volatile("cp.async.wait_group 0;" ::: "memory")

// fp32 -> packed bf16 (hi, lo) for two values; lo = rn(x - hi)
static __device__ __forceinline__ void split2(float x, float y, uint32_t& hi, uint32_t& lo) {
    __nv_bfloat16 hx = __float2bfloat16_rn(x);
    __nv_bfloat16 hy = __float2bfloat16_rn(y);
    float rx = x - __bfloat162float(hx);
    float ry = y - __bfloat162float(hy);
    __nv_bfloat162 h; h.x = hx; h.y = hy;
    __nv_bfloat162 l; l.x = __float2bfloat16_rn(rx); l.y = __float2bfloat16_rn(ry);
    hi = *reinterpret_cast<uint32_t*>(&h);
    lo = *reinterpret_cast<uint32_t*>(&l);
}

// ============ kernel 1: weight conversion (per-launch, deterministic) ============
__global__ __launch_bounds__(256)
void caps_convw(const float* __restrict__ w_img,
                const float* __restrict__ w_capt,
                const float* __restrict__ w_dct)
{
    int gt  = blockIdx.x * 256 + threadIdx.x;     // [0, 147456)
    int mod = gt / 49152;
    int r   = gt % 49152;
    int n   = r / 96;                             // output col within modality [0,512)
    int k8  = r % 96;                             // 8-float k group
    const float* W = (mod == 0) ? w_img : (mod == 1) ? w_capt : w_dct;
    int wrow = ((n & 7) << 6) | (n >> 3);         // W row for col n = r*8 + c
    const float4* src = (const float4*)(W + (size_t)wrow * IN_CH + k8 * 8);
    float4 p = src[0], q = src[1];
    uint32_t h[4], l[4];
    split2(p.x, p.y, h[0], l[0]); split2(p.z, p.w, h[1], l[1]);
    split2(q.x, q.y, h[2], l[2]); split2(q.z, q.w, h[3], l[3]);
    int ntile = n >> 7, rloc = n & 127;
    int kchunk = k8 >> 2, kl = k8 & 3;            // 4 k8-groups per 32-k chunk
    size_t base = (size_t)(((mod * 4 + ntile) * 24 + kchunk) * 2) * PLANE;
    uint32_t off = (uint32_t)(rloc * ROWB + kl * 16);
    *(uint4*)(g_Bscr + base + off)         = make_uint4(h[0], h[1], h[2], h[3]);
    *(uint4*)(g_Bscr + base + PLANE + off) = make_uint4(l[0], l[1], l[2], l[3]);
}

// ============ kernel 2: mma.sync GEMM + bias + squash ============
__global__ __launch_bounds__(256, 2)
void caps_gemm(const float* __restrict__ x_img,
               const float* __restrict__ x_capt,
               const float* __restrict__ x_dct,
               const float* __restrict__ b_img,
               const float* __restrict__ b_capt,
               const float* __restrict__ b_dct,
               float* __restrict__ out)
{
    extern __shared__ __align__(1024) unsigned char smem[];
    const uint32_t sb = s2u(smem);
    float* biasS = (float*)smem;

    const int tid  = threadIdx.x;
    const int lane = tid & 31;
    const int w    = tid >> 5;
    const int wm   = w & 3;            // 4 warps over M (32 rows each)
    const int wn   = w >> 2;           // 2 warps over N (64 cols each)
    const int b0   = blockIdx.x * BM;
    const int n0   = blockIdx.y * BN;
    const int mod  = blockIdx.z;

    const float* X  = (mod == 0) ? x_img : (mod == 1) ? x_capt : x_dct;
    const float* Bv = (mod == 0) ? b_img : (mod == 1) ? b_capt : b_dct;

    if (tid < BN) {
        int n = n0 + tid;
        biasS[tid] = Bv[((n & 7) << 6) + (n >> 3)];
    }

    // ---- A load mapping: thread covers row r = tid>>1, 16 k-floats at half h = tid&1
    const int ar = tid >> 1, ah = tid & 1;
    const float* aG = X + (size_t)(b0 + ar) * IN_CH + ah * 16;
    const uint32_t aS = (uint32_t)(ar * ROWB + ah * 32);    // byte off within plane

    // ---- B cp.async mapping: thread copies 5 x 16B over the 20480B (hi+lo) block
    const unsigned char* bG = g_Bscr + (size_t)((mod * 4 + blockIdx.y) * 24) * 2 * PLANE;

    // ---- ldmatrix lane base offsets (within plane) ----
    const uint32_t a_loff = (uint32_t)((wm * 32 + (lane & 7) + ((lane & 8) ? 8 : 0)) * ROWB
                                       + ((lane & 16) ? 16 : 0));
    const uint32_t b_loff = (uint32_t)((wn * 64 + (lane & 7) + ((lane & 16) ? 8 : 0)) * ROWB
                                       + ((lane & 8) ? 16 : 0));

    float acc[2][8][4];
    #pragma unroll
    for (int i = 0; i < 2; ++i)
        #pragma unroll
        for (int j = 0; j < 8; ++j)
            #pragma unroll
            for (int k = 0; k < 4; ++k) acc[i][j][k] = 0.f;

    // ---- prologue: A(0) regs + B(0) cp.async ----
    float4 av[4];
    #pragma unroll
    for (int j = 0; j < 4; ++j) av[j] = *(const float4*)(aG + j * 4);
    {
        const unsigned char* src = bG;                       // chunk 0, both planes
        uint32_t dst = sb + SM_STG(0) + OFF_BHI;
        #pragma unroll
        for (int j = 0; j < 5; ++j)
            cp16(dst + tid * 16 + j * 4096, src + tid * 16 + j * 4096);
    }
    CP_COMMIT;

    for (int i = 0; i < NCHUNK; ++i) {
        const int s = i & 1;
        const uint32_t stg = sb + SM_STG(s);

        if (i + 1 < NCHUNK) {                                // B(i+1) -> other stage
            const unsigned char* src = bG + (size_t)(i + 1) * 2 * PLANE;
            uint32_t dst = sb + SM_STG(s ^ 1) + OFF_BHI;
            #pragma unroll
            for (int j = 0; j < 5; ++j)
                cp16(dst + tid * 16 + j * 4096, src + tid * 16 + j * 4096);
            CP_COMMIT;
        }

        // STS A(i): split fp32 -> hi/lo planes
        {
            uint32_t hi[8], lo[8];
            #pragma unroll
            for (int j = 0; j < 4; ++j) {
                split2(av[j].x, av[j].y, hi[2*j],   lo[2*j]);
                split2(av[j].z, av[j].w, hi[2*j+1], lo[2*j+1]);
            }
            *(uint4*)(smem + SM_STG(s) + OFF_AHI + aS)      = make_uint4(hi[0], hi[1], hi[2], hi[3]);
            *(uint4*)(smem + SM_STG(s) + OFF_AHI + aS + 16) = make_uint4(hi[4], hi[5], hi[6], hi[7]);
            *(uint4*)(smem + SM_STG(s) + OFF_ALO + aS)      = make_uint4(lo[0], lo[1], lo[2], lo[3]);
            *(uint4*)(smem + SM_STG(s) + OFF_ALO + aS + 16) = make_uint4(lo[4], lo[5], lo[6], lo[7]);
        }
        if (i + 1 < NCHUNK) {                                // prefetch A(i+1)
            const float* ap = aG + (size_t)(i + 1) * BK;
            #pragma unroll
            for (int j = 0; j < 4; ++j) av[j] = *(const float4*)(ap + j * 4);
            CP_WAIT1;
        } else {
            CP_WAIT0;
        }
        __syncthreads();

        // ---- compute chunk i (B frags loaded one g-group at a time: low reg pressure) ----
        #pragma unroll
        for (int st = 0; st < 2; ++st) {
            uint32_t ahf[2][4], alf[2][4];
            #pragma unroll
            for (int mt = 0; mt < 2; ++mt) {
                uint32_t base = stg + a_loff + mt * (16 * ROWB) + st * 32;
                ldsm4(ahf[mt], base + OFF_AHI);
                ldsm4(alf[mt], base + OFF_ALO);
            }
            #pragma unroll
            for (int g = 0; g < 4; ++g) {
                uint32_t bh[4], bl[4];
                uint32_t base = stg + b_loff + g * (16 * ROWB) + st * 32;
                ldsm4(bh, base + OFF_BHI);
                ldsm4(bl, base + OFF_BLO);
                #pragma unroll
                for (int half = 0; half < 2; ++half) {
                    const uint32_t* BH = &bh[half * 2];
                    const uint32_t* BL = &bl[half * 2];
                    #pragma unroll
                    for (int mt = 0; mt < 2; ++mt) {
                        float* c = acc[mt][2 * g + half];
                        mma16816(c, ahf[mt], BH);   // hi*hi
                        mma16816(c, ahf[mt], BL);   // hi*lo
                        mma16816(c, alf[mt], BH);   // lo*hi
                    }
                }
            }
        }
        __syncthreads();
    }

    // ---- epilogue: bias + squash (8-col group == one n8 tile) ----
    const int t4 = lane & 3, g8 = lane >> 2;
    #pragma unroll
    for (int mt = 0; mt < 2; ++mt) {
        const int row0 = b0 + wm * 32 + mt * 16 + g8;
        #pragma unroll
        for (int nt = 0; nt < 8; ++nt) {
            float* c = acc[mt][nt];
            const int cl = wn * 64 + nt * 8 + 2 * t4;        // local col
            const float bx = biasS[cl], by = biasS[cl + 1];
            float u0 = c[0] + bx, u1 = c[1] + by;
            float u2 = c[2] + bx, u3 = c[3] + by;
            float s0 = u0 * u0 + u1 * u1;
            float s1 = u2 * u2 + u3 * u3;
            s0 += __shfl_xor_sync(0xffffffffu, s0, 1);
            s0 += __shfl_xor_sync(0xffffffffu, s0, 2);
            s1 += __shfl_xor_sync(0xffffffffu, s1, 1);
            s1 += __shfl_xor_sync(0xffffffffu, s1, 2);
            float sc0 = s0 / ((1.0f + s0) * sqrtf(s0 + 1e-7f));
            float sc1 = s1 / ((1.0f + s1) * sqrtf(s1 + 1e-7f));
            float* p0 = out + (size_t)row0 * OUT_ROW + mod * 512 + n0 + cl;
            float* p1 = p0 + 8 * OUT_ROW;
            *(float2*)p0 = make_float2(u0 * sc0, u1 * sc0);
            *(float2*)p1 = make_float2(u2 * sc1, u3 * sc1);
        }
    }
}

extern "C" void kernel_launch(void* const* d_in, const int* in_sizes, int n_in,
                              void* d_out, int out_size)
{
    const float* x_img  = (const float*)d_in[0];
    const float* x_capt = (const float*)d_in[1];
    const float* x_dct  = (const float*)d_in[2];
    const float* w_img  = (const float*)d_in[3];
    const float* b_img  = (const float*)d_in[4];
    const float* w_capt = (const float*)d_in[5];
    const float* b_capt = (const float*)d_in[6];
    const float* w_dct  = (const float*)d_in[7];
    const float* b_dct  = (const float*)d_in[8];
    float* out = (float*)d_out;

    cudaFuncSetAttribute(caps_gemm, cudaFuncAttributeMaxDynamicSharedMemorySize, SMEM_TOTAL);

    caps_convw<<<576, 256>>>(w_img, w_capt, w_dct);

    dim3 grid(16384 / BM, 512 / BN, 3);   // (128, 4, 3)
    caps_gemm<<<grid, 256, SMEM_TOTAL>>>(x_img, x_capt, x_dct,
                                         b_img, b_capt, b_dct, out);
}